// round 2
// baseline (speedup 1.0000x reference)
#include <cuda_runtime.h>
#include <math.h>

#define DD 160
typedef unsigned long long u64;

// Scratch for conv output y [B=2, 160,160,160]
static __device__ float g_y[2 * DD * DD * DD];

static __device__ __forceinline__ int clampi(int v) {
    return min(DD - 1, max(0, v));
}

__device__ __forceinline__ u64 pack2(float lo, float hi) {
    u64 r; asm("mov.b64 %0, {%1, %2};" : "=l"(r) : "f"(lo), "f"(hi)); return r;
}
__device__ __forceinline__ void unpack2(u64 v, float &lo, float &hi) {
    asm("mov.b64 {%0, %1}, %2;" : "=f"(lo), "=f"(hi) : "l"(v));
}
__device__ __forceinline__ u64 ffma2(u64 a, u64 b, u64 c) {
    u64 d; asm("fma.rn.f32x2 %0, %1, %2, %3;" : "=l"(d) : "l"(a), "l"(b), "l"(c));
    return d;
}

// ---------------------------------------------------------------------------
// Pass 1: 3D conv 5x5x5, replicate padding, via packed f32x2 FMA.
// Tile: 32x (4 groups * 8 per thread) x 16y x 4z(per thread). 64 threads.
// Smem x tile: 8 z-slices x 20 y-rows x 36 x (stride 37 -> conflict-free).
// Weights pre-packed {w,w} in smem (broadcast LDS.64).
// ---------------------------------------------------------------------------
__global__ __launch_bounds__(64) void conv3d_kernel(
    const float* __restrict__ x, const float* __restrict__ w)
{
    __shared__ float s[8 * 20 * 37];
    __shared__ u64 ws2[125];

    const int tx = threadIdx.x;              // 0..3  (x group)
    const int ty = threadIdx.y;              // 0..15 (y)
    const int tid = ty * 4 + tx;

    const int bx0 = blockIdx.x * 32;
    const int by0 = blockIdx.y * 16;
    const int b   = blockIdx.z / 40;
    const int bz0 = (blockIdx.z % 40) * 4;

    const float* xb = x + (size_t)b * DD * DD * DD;

    for (int i = tid; i < 125; i += 64) {
        float wv = w[i];
        ws2[i] = pack2(wv, wv);
    }

    // Load 8 x 20 x 36 halo tile, replicate-clamped
    for (int idx = tid; idx < 8 * 20 * 36; idx += 64) {
        int sz = idx / (20 * 36);
        int r  = idx % (20 * 36);
        int sy = r / 36;
        int sx = r % 36;
        int gz = clampi(bz0 + sz - 2);
        int gy = clampi(by0 + sy - 2);
        int gx = clampi(bx0 + sx - 2);
        s[sz * 740 + sy * 37 + sx] = xb[((size_t)gz * DD + gy) * DD + gx];
    }
    __syncthreads();

    u64 acc2[4][4];   // [tz][output pair]: outputs (2*o2, 2*o2+1)
#pragma unroll
    for (int a = 0; a < 4; a++)
#pragma unroll
        for (int o = 0; o < 4; o++) acc2[a][o] = 0ull;

    const int xoff = tx * 8;

    for (int sz = 0; sz < 8; sz++) {
#pragma unroll
        for (int dy = 0; dy < 5; dy++) {
            float r[12];
            const float* row = &s[sz * 740 + (ty + dy) * 37 + xoff];
#pragma unroll
            for (int i = 0; i < 12; i++) r[i] = row[i];
            u64 p[11];
#pragma unroll
            for (int i = 0; i < 11; i++) p[i] = pack2(r[i], r[i + 1]);
#pragma unroll
            for (int tz = 0; tz < 4; tz++) {
                int dz = sz - tz;
                if (dz < 0 || dz > 4) continue;
                const u64* wr = &ws2[(dz * 5 + dy) * 5];
                u64 w0 = wr[0], w1 = wr[1], w2 = wr[2], w3 = wr[3], w4 = wr[4];
#pragma unroll
                for (int o2 = 0; o2 < 4; o2++) {
                    u64 a = acc2[tz][o2];
                    a = ffma2(w0, p[o2 * 2 + 0], a);
                    a = ffma2(w1, p[o2 * 2 + 1], a);
                    a = ffma2(w2, p[o2 * 2 + 2], a);
                    a = ffma2(w3, p[o2 * 2 + 3], a);
                    a = ffma2(w4, p[o2 * 2 + 4], a);
                    acc2[tz][o2] = a;
                }
            }
        }
    }

    float* yb = g_y + (size_t)b * DD * DD * DD;
#pragma unroll
    for (int tz = 0; tz < 4; tz++) {
        float* orow = yb + ((size_t)(bz0 + tz) * DD + (by0 + ty)) * DD + bx0 + xoff;
#pragma unroll
        for (int o2 = 0; o2 < 4; o2++) {
            float lo, hi;
            unpack2(acc2[tz][o2], lo, hi);
            float2 v; v.x = lo; v.y = hi;
            ((float2*)orow)[o2] = v;
        }
    }
}

// ---------------------------------------------------------------------------
// Pass 2: Hessian (6 comps) + MLP(6->10 relu ->1 sigmoid) per voxel.
//
// Boundary trick: jnp.gradient's one-sided edge formula equals a central
// difference on a linearly extrapolated ghost layer. With a 2-layer
// linearly-extrapolated halo, ALL 6 components are uniform central stencils;
// the pure second derivatives need a x2 factor at i in {0, DD-1} only.
//
// Tile: 32x x 8y x 4z(per-thread loop). 256 threads.
// Smem y tile: 8 z x 12 y x 36 x (stride 37).
// ---------------------------------------------------------------------------
struct AxW { int i0, i1; float w0, w1; };
static __device__ __forceinline__ AxW axw(int g) {
    AxW a;
    if (g < 0)        { a.i0 = 0;      a.i1 = 1;      a.w0 = (float)(1 - g); a.w1 = (float)g; }
    else if (g >= DD) { int e = g - (DD - 1);
                        a.i0 = DD - 1; a.i1 = DD - 2; a.w0 = (float)(1 + e); a.w1 = (float)(-e); }
    else              { a.i0 = g;      a.i1 = g;      a.w0 = 1.f;            a.w1 = 0.f; }
    return a;
}

__global__ __launch_bounds__(256) void hess_mlp_kernel(
    const float* __restrict__ w1, const float* __restrict__ b1,
    const float* __restrict__ w2, const float* __restrict__ b2,
    float* __restrict__ out)
{
    __shared__ float s[8 * 12 * 37];
    __shared__ float sw1[60], sb1[10], sw2[10], sb2s[1];

    const int tx = threadIdx.x;   // 0..31
    const int ty = threadIdx.y;   // 0..7
    const int tid = ty * 32 + tx;

    const int bx0 = blockIdx.x * 32;
    const int by0 = blockIdx.y * 8;
    const int b   = blockIdx.z / 40;
    const int bz0 = (blockIdx.z % 40) * 4;

    const float* yb = g_y + (size_t)b * DD * DD * DD;

    if (tid < 60)        sw1[tid] = w1[tid];
    else if (tid < 70)   sb1[tid - 60] = b1[tid - 60];
    else if (tid < 80)   sw2[tid - 70] = w2[tid - 70];
    else if (tid == 80)  sb2s[0] = b2[0];

    for (int idx = tid; idx < 8 * 12 * 36; idx += 256) {
        int sz = idx / (12 * 36);
        int r  = idx % (12 * 36);
        int sy = r / 36;
        int sx = r % 36;
        int gz = bz0 + sz - 2;
        int gy = by0 + sy - 2;
        int gx = bx0 + sx - 2;
        float v;
        if ((unsigned)gz < DD && (unsigned)gy < DD && (unsigned)gx < DD) {
            v = yb[((size_t)gz * DD + gy) * DD + gx];
        } else {
            // separable linear extrapolation (trilinear on 2 edge samples/axis)
            AxW az = axw(gz), ay = axw(gy), ax = axw(gx);
            auto F = [&](int z, int y, int xx) {
                return yb[((size_t)z * DD + y) * DD + xx];
            };
            float v00 = ax.w0 * F(az.i0, ay.i0, ax.i0) + ax.w1 * F(az.i0, ay.i0, ax.i1);
            float v01 = ax.w0 * F(az.i0, ay.i1, ax.i0) + ax.w1 * F(az.i0, ay.i1, ax.i1);
            float v10 = ax.w0 * F(az.i1, ay.i0, ax.i0) + ax.w1 * F(az.i1, ay.i0, ax.i1);
            float v11 = ax.w0 * F(az.i1, ay.i1, ax.i0) + ax.w1 * F(az.i1, ay.i1, ax.i1);
            v = az.w0 * (ay.w0 * v00 + ay.w1 * v01) + az.w1 * (ay.w0 * v10 + ay.w1 * v11);
        }
        s[sz * 444 + sy * 37 + sx] = v;
    }
    __syncthreads();

    const int gx = bx0 + tx;
    const int gy = by0 + ty;
    const float fy = (gy == 0 || gy == DD - 1) ? 2.f : 1.f;
    const float fx = (gx == 0 || gx == DD - 1) ? 2.f : 1.f;

    float h[4][6];
#pragma unroll
    for (int tz = 0; tz < 4; tz++) {
        const int gz = bz0 + tz;
        const float fz = (gz == 0 || gz == DD - 1) ? 2.f : 1.f;
        const float* c = &s[(tz + 2) * 444 + (ty + 2) * 37 + (tx + 2)];

        float cc = c[0];
        h[tz][0] = fz * 0.25f * (c[2 * 444] - 2.f * cc + c[-2 * 444]);                    // zz
        h[tz][1] = 0.25f * (c[444 + 37] - c[444 - 37] - c[-444 + 37] + c[-444 - 37]);     // zy
        h[tz][2] = 0.25f * (c[444 + 1] - c[444 - 1] - c[-444 + 1] + c[-444 - 1]);         // zx
        h[tz][3] = fy * 0.25f * (c[2 * 37] - 2.f * cc + c[-2 * 37]);                      // yy
        h[tz][4] = 0.25f * (c[37 + 1] - c[37 - 1] - c[-37 + 1] + c[-37 - 1]);             // yx
        h[tz][5] = fx * 0.25f * (c[2] - 2.f * cc + c[-2]);                                // xx
    }

    // MLP: z1 = relu(W1 h + b1); out = sigmoid(W2 z1 + b2)
    float a2[4];
#pragma unroll
    for (int v = 0; v < 4; v++) a2[v] = sb2s[0];

#pragma unroll
    for (int o = 0; o < 10; o++) {
        float wr[6];
#pragma unroll
        for (int f = 0; f < 6; f++) wr[f] = sw1[o * 6 + f];
        const float bo  = sb1[o];
        const float w2o = sw2[o];
#pragma unroll
        for (int v = 0; v < 4; v++) {
            float t = bo;
#pragma unroll
            for (int f = 0; f < 6; f++) t = fmaf(wr[f], h[v][f], t);
            t = fmaxf(t, 0.f);
            a2[v] = fmaf(w2o, t, a2[v]);
        }
    }

#pragma unroll
    for (int tz = 0; tz < 4; tz++) {
        float sg = 1.f / (1.f + __expf(-a2[tz]));
        out[(((size_t)b * DD + (bz0 + tz)) * DD + gy) * DD + gx] = sg;
    }
}

// ---------------------------------------------------------------------------
// Launch: inputs per metadata order: x, conv_w, w1, b1, w2, b2
// ---------------------------------------------------------------------------
extern "C" void kernel_launch(void* const* d_in, const int* in_sizes, int n_in,
                              void* d_out, int out_size)
{
    const float* x  = (const float*)d_in[0];
    const float* cw = (const float*)d_in[1];
    const float* w1 = (const float*)d_in[2];
    const float* b1 = (const float*)d_in[3];
    const float* w2 = (const float*)d_in[4];
    const float* b2 = (const float*)d_in[5];
    float* out = (float*)d_out;

    conv3d_kernel<<<dim3(5, 10, 80), dim3(4, 16, 1)>>>(x, cw);
    hess_mlp_kernel<<<dim3(5, 20, 80), dim3(32, 8, 1)>>>(w1, b1, w2, b2, out);
}

// round 3
// speedup vs baseline: 1.2250x; 1.2250x over previous
#include <cuda_runtime.h>
#include <math.h>

#define DD 160
typedef unsigned long long u64;

// Scratch for conv output y [B=2, 160,160,160]
static __device__ float g_y[2 * DD * DD * DD];

static __device__ __forceinline__ int clampi(int v) {
    return min(DD - 1, max(0, v));
}

__device__ __forceinline__ u64 pack2(float lo, float hi) {
    u64 r; asm("mov.b64 %0, {%1, %2};" : "=l"(r) : "f"(lo), "f"(hi)); return r;
}
__device__ __forceinline__ void unpack2(u64 v, float &lo, float &hi) {
    asm("mov.b64 {%0, %1}, %2;" : "=f"(lo), "=f"(hi) : "l"(v));
}
__device__ __forceinline__ u64 ffma2(u64 a, u64 b, u64 c) {
    u64 d; asm("fma.rn.f32x2 %0, %1, %2, %3;" : "=l"(d) : "l"(a), "l"(b), "l"(c));
    return d;
}

// ---------------------------------------------------------------------------
// Pass 1: 3D conv 5x5x5, replicate padding (R1 scalar version — known good).
// Tile: 32x (4 groups * 8 per thread) x 16y x 4z(per thread). 64 threads.
// Smem x tile: 8 z-slices x 20 y-rows x 36 x (stride 37 -> conflict-free).
// ---------------------------------------------------------------------------
__global__ __launch_bounds__(64) void conv3d_kernel(
    const float* __restrict__ x, const float* __restrict__ w)
{
    __shared__ float s[8 * 20 * 37];
    __shared__ float ws[125];

    const int tx = threadIdx.x;              // 0..3  (x group)
    const int ty = threadIdx.y;              // 0..15 (y)
    const int tid = ty * 4 + tx;

    const int bx0 = blockIdx.x * 32;
    const int by0 = blockIdx.y * 16;
    const int b   = blockIdx.z / 40;
    const int bz0 = (blockIdx.z % 40) * 4;

    const float* xb = x + (size_t)b * DD * DD * DD;

    for (int i = tid; i < 125; i += 64) ws[i] = w[i];

    for (int idx = tid; idx < 8 * 20 * 36; idx += 64) {
        int sz = idx / (20 * 36);
        int r  = idx % (20 * 36);
        int sy = r / 36;
        int sx = r % 36;
        int gz = clampi(bz0 + sz - 2);
        int gy = clampi(by0 + sy - 2);
        int gx = clampi(bx0 + sx - 2);
        s[sz * 740 + sy * 37 + sx] = xb[((size_t)gz * DD + gy) * DD + gx];
    }
    __syncthreads();

    float acc[4][8];
#pragma unroll
    for (int a = 0; a < 4; a++)
#pragma unroll
        for (int o = 0; o < 8; o++) acc[a][o] = 0.f;

    const int xoff = tx * 8;

    for (int sz = 0; sz < 8; sz++) {
#pragma unroll
        for (int dy = 0; dy < 5; dy++) {
            float r[12];
            const float* row = &s[sz * 740 + (ty + dy) * 37 + xoff];
#pragma unroll
            for (int i = 0; i < 12; i++) r[i] = row[i];
#pragma unroll
            for (int tz = 0; tz < 4; tz++) {
                int dz = sz - tz;
                if (dz < 0 || dz > 4) continue;
                const float* wr = &ws[(dz * 5 + dy) * 5];
                float w0 = wr[0], w1 = wr[1], w2 = wr[2], w3 = wr[3], w4 = wr[4];
#pragma unroll
                for (int o = 0; o < 8; o++) {
                    float a = acc[tz][o];
                    a = fmaf(w0, r[o + 0], a);
                    a = fmaf(w1, r[o + 1], a);
                    a = fmaf(w2, r[o + 2], a);
                    a = fmaf(w3, r[o + 3], a);
                    a = fmaf(w4, r[o + 4], a);
                    acc[tz][o] = a;
                }
            }
        }
    }

    float* yb = g_y + (size_t)b * DD * DD * DD;
#pragma unroll
    for (int tz = 0; tz < 4; tz++) {
        float* orow = yb + ((size_t)(bz0 + tz) * DD + (by0 + ty)) * DD + bx0 + xoff;
#pragma unroll
        for (int o = 0; o < 8; o++) orow[o] = acc[tz][o];
    }
}

// ---------------------------------------------------------------------------
// Pass 2: Hessian (6 comps) + MLP(6->10 relu ->1 sigmoid) per voxel.
//
// jnp.gradient edge handling == central differences on a linearly
// extrapolated 2-layer ghost halo, with a x2 factor on PURE second
// derivatives at coordinate 0 / DD-1 (verified in R2, rel_err 5.8e-8).
// Here: load halo CLAMPED (cheap), then overwrite only ghost cells in smem
// via 3 separable fixup passes (x, then y, then z). Fixups only execute in
// boundary blocks (block-uniform conditions).
//
// Tile: 32x x 8y x 4z(per-thread). 256 threads. Smem: 8z x 12y x 36x (stride 37).
// ---------------------------------------------------------------------------
__global__ __launch_bounds__(256) void hess_mlp_kernel(
    const float* __restrict__ w1, const float* __restrict__ b1,
    const float* __restrict__ w2, const float* __restrict__ b2,
    float* __restrict__ out)
{
    __shared__ float s[8 * 12 * 37];
    __shared__ u64 sw1p[60], sb1p[10];
    __shared__ float sw2[10], sb2s[1];

    const int tx = threadIdx.x;   // 0..31
    const int ty = threadIdx.y;   // 0..7
    const int tid = ty * 32 + tx;

    const int bx0 = blockIdx.x * 32;
    const int by0 = blockIdx.y * 8;
    const int b   = blockIdx.z / 40;
    const int bz0 = (blockIdx.z % 40) * 4;

    const float* yb = g_y + (size_t)b * DD * DD * DD;

    if (tid < 60)        { float v = w1[tid];      sw1p[tid] = pack2(v, v); }
    else if (tid < 70)   { float v = b1[tid - 60]; sb1p[tid - 60] = pack2(v, v); }
    else if (tid < 80)   sw2[tid - 70] = w2[tid - 70];
    else if (tid == 80)  sb2s[0] = b2[0];

    // Clamped halo load
    for (int idx = tid; idx < 8 * 12 * 36; idx += 256) {
        int sz = idx / (12 * 36);
        int r  = idx % (12 * 36);
        int sy = r / 36;
        int sx = r % 36;
        int gz = clampi(bz0 + sz - 2);
        int gy = clampi(by0 + sy - 2);
        int gx = clampi(bx0 + sx - 2);
        s[sz * 444 + sy * 37 + sx] = yb[((size_t)gz * DD + gy) * DD + gx];
    }
    __syncthreads();

    // Ghost-cell fixups: convert clamped halo -> linearly extrapolated halo.
    // Conditions are block-uniform, so conditional __syncthreads is legal.
    const bool bxL = (bx0 == 0), bxR = (bx0 + 32 == DD);
    const bool byL = (by0 == 0), byR = (by0 + 8 == DD);
    const bool bzL = (bz0 == 0), bzR = (bz0 + 4 == DD);

    if (bxL | bxR) {
        if (tid < 96) {   // 8z * 12y rows
            int z = tid >> 2;          // wrong decomp avoided: use div by 12
            z = tid / 12;
            int y = tid - z * 12;
            float* row = &s[z * 444 + y * 37];
            if (bxL) { float a = row[2],  bb = row[3];
                       row[1] = 2.f * a - bb; row[0] = 3.f * a - 2.f * bb; }
            if (bxR) { float a = row[33], bb = row[32];
                       row[34] = 2.f * a - bb; row[35] = 3.f * a - 2.f * bb; }
        }
        __syncthreads();
    }
    if (byL | byR) {
        for (int idx = tid; idx < 8 * 36; idx += 256) {  // 288 columns
            int z = idx / 36;
            int xx = idx - z * 36;
            float* p = &s[z * 444 + xx];
            if (byL) { float a = p[2 * 37], bb = p[3 * 37];
                       p[1 * 37] = 2.f * a - bb; p[0] = 3.f * a - 2.f * bb; }
            if (byR) { float a = p[9 * 37], bb = p[8 * 37];
                       p[10 * 37] = 2.f * a - bb; p[11 * 37] = 3.f * a - 2.f * bb; }
        }
        __syncthreads();
    }
    if (bzL | bzR) {
        for (int idx = tid; idx < 12 * 36; idx += 256) { // 432 columns
            int y = idx / 36;
            int xx = idx - y * 36;
            float* p = &s[y * 37 + xx];
            if (bzL) { float a = p[2 * 444], bb = p[3 * 444];
                       p[1 * 444] = 2.f * a - bb; p[0] = 3.f * a - 2.f * bb; }
            if (bzR) { float a = p[5 * 444], bb = p[4 * 444];
                       p[6 * 444] = 2.f * a - bb; p[7 * 444] = 3.f * a - 2.f * bb; }
        }
        __syncthreads();
    }

    const int gx = bx0 + tx;
    const int gy = by0 + ty;
    const float fy = (gy == 0 || gy == DD - 1) ? 2.f : 1.f;
    const float fx = (gx == 0 || gx == DD - 1) ? 2.f : 1.f;

    float h[4][6];
#pragma unroll
    for (int tz = 0; tz < 4; tz++) {
        const int gz = bz0 + tz;
        const float fz = (gz == 0 || gz == DD - 1) ? 2.f : 1.f;
        const float* c = &s[(tz + 2) * 444 + (ty + 2) * 37 + (tx + 2)];

        float cc = c[0];
        h[tz][0] = fz * 0.25f * (c[2 * 444] - 2.f * cc + c[-2 * 444]);                // zz
        h[tz][1] = 0.25f * (c[444 + 37] - c[444 - 37] - c[-444 + 37] + c[-444 - 37]); // zy
        h[tz][2] = 0.25f * (c[444 + 1] - c[444 - 1] - c[-444 + 1] + c[-444 - 1]);     // zx
        h[tz][3] = fy * 0.25f * (c[2 * 37] - 2.f * cc + c[-2 * 37]);                  // yy
        h[tz][4] = 0.25f * (c[37 + 1] - c[37 - 1] - c[-37 + 1] + c[-37 - 1]);         // yx
        h[tz][5] = fx * 0.25f * (c[2] - 2.f * cc + c[-2]);                            // xx
    }

    // MLP: layer1 packed f32x2 over voxel pairs (z0,z1) and (z2,z3).
    u64 hp[2][6];
#pragma unroll
    for (int p = 0; p < 2; p++)
#pragma unroll
        for (int f = 0; f < 6; f++) hp[p][f] = pack2(h[2 * p][f], h[2 * p + 1][f]);

    float a2[4];
#pragma unroll
    for (int v = 0; v < 4; v++) a2[v] = sb2s[0];

#pragma unroll
    for (int o = 0; o < 10; o++) {
        u64 t0 = sb1p[o], t1 = t0;
#pragma unroll
        for (int f = 0; f < 6; f++) {
            u64 wv = sw1p[o * 6 + f];
            t0 = ffma2(wv, hp[0][f], t0);
            t1 = ffma2(wv, hp[1][f], t1);
        }
        float u0, v0, u1, v1;
        unpack2(t0, u0, v0);
        unpack2(t1, u1, v1);
        const float w2o = sw2[o];
        a2[0] = fmaf(w2o, fmaxf(u0, 0.f), a2[0]);
        a2[1] = fmaf(w2o, fmaxf(v0, 0.f), a2[1]);
        a2[2] = fmaf(w2o, fmaxf(u1, 0.f), a2[2]);
        a2[3] = fmaf(w2o, fmaxf(v1, 0.f), a2[3]);
    }

#pragma unroll
    for (int tz = 0; tz < 4; tz++) {
        float sg = 1.f / (1.f + __expf(-a2[tz]));
        out[(((size_t)b * DD + (bz0 + tz)) * DD + gy) * DD + gx] = sg;
    }
}

// ---------------------------------------------------------------------------
// Launch: inputs per metadata order: x, conv_w, w1, b1, w2, b2
// ---------------------------------------------------------------------------
extern "C" void kernel_launch(void* const* d_in, const int* in_sizes, int n_in,
                              void* d_out, int out_size)
{
    const float* x  = (const float*)d_in[0];
    const float* cw = (const float*)d_in[1];
    const float* w1 = (const float*)d_in[2];
    const float* b1 = (const float*)d_in[3];
    const float* w2 = (const float*)d_in[4];
    const float* b2 = (const float*)d_in[5];
    float* out = (float*)d_out;

    conv3d_kernel<<<dim3(5, 10, 80), dim3(4, 16, 1)>>>(x, cw);
    hess_mlp_kernel<<<dim3(5, 20, 80), dim3(32, 8, 1)>>>(w1, b1, w2, b2, out);
}

// round 4
// speedup vs baseline: 1.6148x; 1.3181x over previous
#include <cuda_runtime.h>
#include <math.h>

#define DD 160
#define SL 740   // slice floats: 20 rows * 37 stride (36 used)

// Scratch for conv output y [B=2, 160,160,160]
static __device__ float g_y[2 * DD * DD * DD];

static __device__ __forceinline__ int clampi(int v) {
    return min(DD - 1, max(0, v));
}

// ---------------------------------------------------------------------------
// Pass 1: 3D conv 5x5x5, replicate padding (R1 scalar — known good, 83us).
// ---------------------------------------------------------------------------
__global__ __launch_bounds__(64) void conv3d_kernel(
    const float* __restrict__ x, const float* __restrict__ w)
{
    __shared__ float s[8 * 20 * 37];
    __shared__ float ws[125];

    const int tx = threadIdx.x;              // 0..3
    const int ty = threadIdx.y;              // 0..15
    const int tid = ty * 4 + tx;

    const int bx0 = blockIdx.x * 32;
    const int by0 = blockIdx.y * 16;
    const int b   = blockIdx.z / 40;
    const int bz0 = (blockIdx.z % 40) * 4;

    const float* xb = x + (size_t)b * DD * DD * DD;

    for (int i = tid; i < 125; i += 64) ws[i] = w[i];

    for (int idx = tid; idx < 8 * 20 * 36; idx += 64) {
        int sz = idx / (20 * 36);
        int r  = idx % (20 * 36);
        int sy = r / 36;
        int sx = r % 36;
        int gz = clampi(bz0 + sz - 2);
        int gy = clampi(by0 + sy - 2);
        int gx = clampi(bx0 + sx - 2);
        s[sz * 740 + sy * 37 + sx] = xb[((size_t)gz * DD + gy) * DD + gx];
    }
    __syncthreads();

    float acc[4][8];
#pragma unroll
    for (int a = 0; a < 4; a++)
#pragma unroll
        for (int o = 0; o < 8; o++) acc[a][o] = 0.f;

    const int xoff = tx * 8;

    for (int sz = 0; sz < 8; sz++) {
#pragma unroll
        for (int dy = 0; dy < 5; dy++) {
            float r[12];
            const float* row = &s[sz * 740 + (ty + dy) * 37 + xoff];
#pragma unroll
            for (int i = 0; i < 12; i++) r[i] = row[i];
#pragma unroll
            for (int tz = 0; tz < 4; tz++) {
                int dz = sz - tz;
                if (dz < 0 || dz > 4) continue;
                const float* wr = &ws[(dz * 5 + dy) * 5];
                float w0 = wr[0], w1 = wr[1], w2 = wr[2], w3 = wr[3], w4 = wr[4];
#pragma unroll
                for (int o = 0; o < 8; o++) {
                    float a = acc[tz][o];
                    a = fmaf(w0, r[o + 0], a);
                    a = fmaf(w1, r[o + 1], a);
                    a = fmaf(w2, r[o + 2], a);
                    a = fmaf(w3, r[o + 3], a);
                    a = fmaf(w4, r[o + 4], a);
                    acc[tz][o] = a;
                }
            }
        }
    }

    float* yb = g_y + (size_t)b * DD * DD * DD;
#pragma unroll
    for (int tz = 0; tz < 4; tz++) {
        float* orow = yb + ((size_t)(bz0 + tz) * DD + (by0 + ty)) * DD + bx0 + xoff;
#pragma unroll
        for (int o = 0; o < 8; o++) orow[o] = acc[tz][o];
    }
}

// ---------------------------------------------------------------------------
// Pass 2: z-marching Hessian + MLP.
// Block: 128 threads (32 tx x 4 tyq). Tile 32x x 16y, marches 20 z-layers.
// Ring of 8 slices (20y x 37 stride) in smem.
// Ghost handling (verified): jnp.gradient edges == central diff on linearly
// extrapolated halo; pure 2nd derivs get x2 at coord 0/DD-1. z-ghosts are
// extrapolated in the loader; x/y ghosts via warp-0 smem fixups (edge blocks).
// ---------------------------------------------------------------------------
__global__ __launch_bounds__(128) void hess_mlp_kernel(
    const float* __restrict__ w1, const float* __restrict__ b1,
    const float* __restrict__ w2, const float* __restrict__ b2,
    float* __restrict__ out)
{
    __shared__ float s[8 * SL];
    __shared__ float sw1[60], sb1[10], sw2[10], sb2s[1];

    const int tx  = threadIdx.x;   // 0..31
    const int tyq = threadIdx.y;   // 0..3 (warp id)
    const int tid = tyq * 32 + tx;

    const int bx0 = blockIdx.x * 32;
    const int by0 = blockIdx.y * 16;
    const int b   = blockIdx.z >> 3;
    const int z0  = (blockIdx.z & 7) * 20;

    const float* yb = g_y + (size_t)b * DD * DD * DD;

    if (tid < 60)       sw1[tid] = w1[tid];
    else if (tid < 70)  sb1[tid - 60] = b1[tid - 60];
    else if (tid < 80)  sw2[tid - 70] = w2[tid - 70];
    else if (tid == 80) sb2s[0] = b2[0];

    // Per-thread load table: 720 slice elems / 128 threads (computed once)
    int lsm[6], lgm[6];
#pragma unroll
    for (int k = 0; k < 6; k++) {
        int idx = tid + k * 128;
        if (idx < 720) {
            int sy = idx / 36, sx = idx - sy * 36;
            int gy = clampi(by0 + sy - 2);
            int gx = clampi(bx0 + sx - 2);
            lsm[k] = sy * 37 + sx;
            lgm[k] = gy * DD + gx;
        } else { lsm[k] = -1; lgm[k] = 0; }
    }

    const bool bxL = (bx0 == 0), bxR = (bx0 + 32 == DD);
    const bool byL = (by0 == 0), byR = (by0 + 16 == DD);
    const bool edge = bxL | bxR | byL | byR;

    auto load_slice = [&](int gz, float* dst) {
        if ((unsigned)gz < DD) {
            const float* base = yb + (size_t)gz * (DD * DD);
#pragma unroll
            for (int k = 0; k < 6; k++)
                if (lsm[k] >= 0) dst[lsm[k]] = __ldg(base + lgm[k]);
        } else {
            int e; const float *p0, *p1;
            if (gz < 0) { e = -gz; p0 = yb; p1 = yb + DD * DD; }
            else        { e = gz - (DD - 1);
                          p0 = yb + (size_t)(DD - 1) * DD * DD;
                          p1 = yb + (size_t)(DD - 2) * DD * DD; }
            float w0 = 1.f + (float)e, w1n = -(float)e;
#pragma unroll
            for (int k = 0; k < 6; k++)
                if (lsm[k] >= 0)
                    dst[lsm[k]] = w0 * __ldg(p0 + lgm[k]) + w1n * __ldg(p1 + lgm[k]);
        }
    };

    // warp-0 only (tid<32): x-extrap then y-extrap of ghost cells
    auto fixup = [&](float* sl) {
        if (bxL | bxR) {
            if (tx < 20) {
                float* row = sl + tx * 37;
                if (bxL) { float a = row[2],  c2 = row[3];
                           row[1]  = 2.f * a - c2; row[0]  = 3.f * a - 2.f * c2; }
                if (bxR) { float a = row[33], c2 = row[32];
                           row[34] = 2.f * a - c2; row[35] = 3.f * a - 2.f * c2; }
            }
            __syncwarp();
        }
        if (byL | byR) {
            for (int xx = tx; xx < 36; xx += 32) {
                float* p = sl + xx;
                if (byL) { float a = p[2 * 37],  c2 = p[3 * 37];
                           p[37]      = 2.f * a - c2; p[0]       = 3.f * a - 2.f * c2; }
                if (byR) { float a = p[17 * 37], c2 = p[16 * 37];
                           p[18 * 37] = 2.f * a - c2; p[19 * 37] = 3.f * a - 2.f * c2; }
            }
        }
    };

    // Preload slices gz = z0-2 .. z0+1  (slot(gz) = (gz+16) & 7)
    for (int gz = z0 - 2; gz <= z0 + 1; gz++)
        load_slice(gz, s + ((gz + 16) & 7) * SL);
    __syncthreads();
    if (edge) {
        if (tid < 32)
            for (int gz = z0 - 2; gz <= z0 + 1; gz++)
                fixup(s + ((gz + 16) & 7) * SL);
        __syncthreads();
    }

    const int gx = bx0 + tx;
    const float fxc = (gx == 0 || gx == DD - 1) ? 2.f : 1.f;
    const int y4 = tyq * 4;
    const int coff = (y4 + 2) * 37 + tx + 2;

    for (int z = z0; z < z0 + 20; z++) {
        load_slice(z + 2, s + ((z + 18) & 7) * SL);
        __syncthreads();
        if (edge) {
            if (tid < 32) fixup(s + ((z + 18) & 7) * SL);
            __syncthreads();
        }

        const float* sm2 = s + ((z + 14) & 7) * SL;
        const float* sm1 = s + ((z + 15) & 7) * SL;
        const float* sc  = s + ((z + 16) & 7) * SL;
        const float* sp1 = s + ((z + 17) & 7) * SL;
        const float* sp2 = s + ((z + 18) & 7) * SL;
        const float fz = (z == 0 || z == DD - 1) ? 2.f : 1.f;

        float h[4][6];
#pragma unroll
        for (int v = 0; v < 4; v++) {
            const int c = coff + v * 37;
            const int gy = by0 + y4 + v;
            const float fy = (gy == 0 || gy == DD - 1) ? 2.f : 1.f;
            float cc = sc[c];
            h[v][0] = fz * 0.25f * (sp2[c] - 2.f * cc + sm2[c]);                       // zz
            h[v][1] = 0.25f * (sp1[c + 37] - sp1[c - 37] - sm1[c + 37] + sm1[c - 37]); // zy
            h[v][2] = 0.25f * (sp1[c + 1] - sp1[c - 1] - sm1[c + 1] + sm1[c - 1]);     // zx
            h[v][3] = fy * 0.25f * (sc[c + 74] - 2.f * cc + sc[c - 74]);               // yy
            h[v][4] = 0.25f * (sc[c + 38] - sc[c + 36] - sc[c - 36] + sc[c - 38]);     // yx
            h[v][5] = fxc * 0.25f * (sc[c + 2] - 2.f * cc + sc[c - 2]);                // xx
        }

        float a2[4];
#pragma unroll
        for (int v = 0; v < 4; v++) a2[v] = sb2s[0];

#pragma unroll
        for (int o = 0; o < 10; o++) {
            float wr0 = sw1[o * 6 + 0], wr1 = sw1[o * 6 + 1], wr2 = sw1[o * 6 + 2];
            float wr3 = sw1[o * 6 + 3], wr4 = sw1[o * 6 + 4], wr5 = sw1[o * 6 + 5];
            const float bo  = sb1[o];
            const float w2o = sw2[o];
#pragma unroll
            for (int v = 0; v < 4; v++) {
                float t = bo;
                t = fmaf(wr0, h[v][0], t);
                t = fmaf(wr1, h[v][1], t);
                t = fmaf(wr2, h[v][2], t);
                t = fmaf(wr3, h[v][3], t);
                t = fmaf(wr4, h[v][4], t);
                t = fmaf(wr5, h[v][5], t);
                a2[v] = fmaf(w2o, fmaxf(t, 0.f), a2[v]);
            }
        }

#pragma unroll
        for (int v = 0; v < 4; v++) {
            float sg = 1.f / (1.f + __expf(-a2[v]));
            out[(((size_t)b * DD + z) * DD + (by0 + y4 + v)) * DD + gx] = sg;
        }
    }
}

// ---------------------------------------------------------------------------
// Launch: inputs per metadata order: x, conv_w, w1, b1, w2, b2
// ---------------------------------------------------------------------------
extern "C" void kernel_launch(void* const* d_in, const int* in_sizes, int n_in,
                              void* d_out, int out_size)
{
    const float* x  = (const float*)d_in[0];
    const float* cw = (const float*)d_in[1];
    const float* w1 = (const float*)d_in[2];
    const float* b1 = (const float*)d_in[3];
    const float* w2 = (const float*)d_in[4];
    const float* b2 = (const float*)d_in[5];
    float* out = (float*)d_out;

    conv3d_kernel<<<dim3(5, 10, 80), dim3(4, 16, 1)>>>(x, cw);
    // hess: grid x:5, y:160/16=10, z: 2 batches * 8 z-chunks of 20
    hess_mlp_kernel<<<dim3(5, 10, 16), dim3(32, 4, 1)>>>(w1, b1, w2, b2, out);
}

// round 5
// speedup vs baseline: 1.8166x; 1.1250x over previous
#include <cuda_runtime.h>
#include <math.h>

#define DD 160
#define SL 740        // hess slice: 20 rows * 37 stride
#define CSL (36*40)   // conv slice: 36 rows * 40 stride

// Scratch for conv output y [B=2, 160,160,160]
static __device__ float g_y[2 * DD * DD * DD];

static __device__ __forceinline__ int clampi(int v) {
    return min(DD - 1, max(0, v));
}

// ---------------------------------------------------------------------------
// Pass 1: z-marching 3D conv 5x5x5, replicate padding.
// Block 128 thr (4tx x 32ty). Tile 32x x 32y, marches 20 z (+4 warmup).
// Rolling acc[5][8]; 2-slot smem ring (only newest slice is read).
// ---------------------------------------------------------------------------
__global__ __launch_bounds__(128) void conv3d_kernel(
    const float* __restrict__ x, const float* __restrict__ w)
{
    __shared__ float s[2 * CSL];      // 11.5 KB
    __shared__ float wsp[25 * 8];     // weight rows padded to stride 8

    const int tx  = threadIdx.x;      // 0..3 (x group of 8)
    const int ty  = threadIdx.y;      // 0..31
    const int tid = ty * 4 + tx;

    const int bx0 = blockIdx.x * 32;
    const int by0 = blockIdx.y * 32;
    const int b   = blockIdx.z >> 3;
    const int z0  = (blockIdx.z & 7) * 20;

    const float* xb = x + (size_t)b * DD * DD * DD;
    float* yb = g_y + (size_t)b * DD * DD * DD;

    if (tid < 125) wsp[(tid / 5) * 8 + tid % 5] = w[tid];

    // Load table: 36*36 = 1296 slice elems / 128 threads -> 11 entries
    int lsm[11], lgm[11];
#pragma unroll
    for (int k = 0; k < 11; k++) {
        int idx = tid + k * 128;
        if (idx < 1296) {
            int sy = idx / 36, sx = idx - sy * 36;
            lsm[k] = sy * 40 + sx;
            lgm[k] = clampi(by0 + sy - 2) * DD + clampi(bx0 + sx - 2);
        } else lsm[k] = -1;
    }

    float acc[5][8];
#pragma unroll
    for (int g = 0; g < 5; g++)
#pragma unroll
        for (int o = 0; o < 8; o++) acc[g][o] = 0.f;

    const int xoff = tx * 8;
    const int rowbase = ty * 40 + xoff;

    for (int i = 0; i < 24; i++) {            // step z = z0-4+i
        const int z = z0 - 4 + i;
        float* snew = s + (i & 1) * CSL;
        {   // load slice z+2 (clamped)
            const float* base = xb + (size_t)clampi(z + 2) * (DD * DD);
#pragma unroll
            for (int k = 0; k < 11; k++)
                if (lsm[k] >= 0) snew[lsm[k]] = __ldg(base + lgm[k]);
        }
        __syncthreads();

#pragma unroll
        for (int dy = 0; dy < 5; dy++) {
            const float* row = snew + rowbase + dy * 40;
            float4 ra = *(const float4*)(row);
            float4 rb = *(const float4*)(row + 4);
            float4 rc = *(const float4*)(row + 8);
            float r[12] = {ra.x, ra.y, ra.z, ra.w, rb.x, rb.y, rb.z, rb.w,
                           rc.x, rc.y, rc.z, rc.w};
#pragma unroll
            for (int g = 0; g < 5; g++) {
                const float* wr = wsp + ((4 - g) * 5 + dy) * 8;
                float4 wv = *(const float4*)wr;
                float w4 = wr[4];
#pragma unroll
                for (int o = 0; o < 8; o++) {
                    float a = acc[g][o];
                    a = fmaf(wv.x, r[o + 0], a);
                    a = fmaf(wv.y, r[o + 1], a);
                    a = fmaf(wv.z, r[o + 2], a);
                    a = fmaf(wv.w, r[o + 3], a);
                    a = fmaf(w4,   r[o + 4], a);
                    acc[g][o] = a;
                }
            }
        }

        if (z >= z0) {
            float* orow = yb + (((size_t)z * DD) + (by0 + ty)) * DD + bx0 + xoff;
            float4 v0 = {acc[0][0], acc[0][1], acc[0][2], acc[0][3]};
            float4 v1 = {acc[0][4], acc[0][5], acc[0][6], acc[0][7]};
            ((float4*)orow)[0] = v0;
            ((float4*)orow)[1] = v1;
        }
#pragma unroll
        for (int g = 0; g < 4; g++)
#pragma unroll
            for (int o = 0; o < 8; o++) acc[g][o] = acc[g + 1][o];
#pragma unroll
        for (int o = 0; o < 8; o++) acc[4][o] = 0.f;
    }
}

// ---------------------------------------------------------------------------
// Pass 2: z-marching Hessian + MLP (unchanged from R4, 68.6us).
// ---------------------------------------------------------------------------
__global__ __launch_bounds__(128) void hess_mlp_kernel(
    const float* __restrict__ w1, const float* __restrict__ b1,
    const float* __restrict__ w2, const float* __restrict__ b2,
    float* __restrict__ out)
{
    __shared__ float s[8 * SL];
    __shared__ float sw1[60], sb1[10], sw2[10], sb2s[1];

    const int tx  = threadIdx.x;   // 0..31
    const int tyq = threadIdx.y;   // 0..3 (warp id)
    const int tid = tyq * 32 + tx;

    const int bx0 = blockIdx.x * 32;
    const int by0 = blockIdx.y * 16;
    const int b   = blockIdx.z >> 3;
    const int z0  = (blockIdx.z & 7) * 20;

    const float* yb = g_y + (size_t)b * DD * DD * DD;

    if (tid < 60)       sw1[tid] = w1[tid];
    else if (tid < 70)  sb1[tid - 60] = b1[tid - 60];
    else if (tid < 80)  sw2[tid - 70] = w2[tid - 70];
    else if (tid == 80) sb2s[0] = b2[0];

    int lsm[6], lgm[6];
#pragma unroll
    for (int k = 0; k < 6; k++) {
        int idx = tid + k * 128;
        if (idx < 720) {
            int sy = idx / 36, sx = idx - sy * 36;
            lsm[k] = sy * 37 + sx;
            lgm[k] = clampi(by0 + sy - 2) * DD + clampi(bx0 + sx - 2);
        } else { lsm[k] = -1; lgm[k] = 0; }
    }

    const bool bxL = (bx0 == 0), bxR = (bx0 + 32 == DD);
    const bool byL = (by0 == 0), byR = (by0 + 16 == DD);
    const bool edge = bxL | bxR | byL | byR;

    auto load_slice = [&](int gz, float* dst) {
        if ((unsigned)gz < DD) {
            const float* base = yb + (size_t)gz * (DD * DD);
#pragma unroll
            for (int k = 0; k < 6; k++)
                if (lsm[k] >= 0) dst[lsm[k]] = __ldg(base + lgm[k]);
        } else {
            int e; const float *p0, *p1;
            if (gz < 0) { e = -gz; p0 = yb; p1 = yb + DD * DD; }
            else        { e = gz - (DD - 1);
                          p0 = yb + (size_t)(DD - 1) * DD * DD;
                          p1 = yb + (size_t)(DD - 2) * DD * DD; }
            float w0 = 1.f + (float)e, w1n = -(float)e;
#pragma unroll
            for (int k = 0; k < 6; k++)
                if (lsm[k] >= 0)
                    dst[lsm[k]] = w0 * __ldg(p0 + lgm[k]) + w1n * __ldg(p1 + lgm[k]);
        }
    };

    auto fixup = [&](float* sl) {
        if (bxL | bxR) {
            if (tx < 20) {
                float* row = sl + tx * 37;
                if (bxL) { float a = row[2],  c2 = row[3];
                           row[1]  = 2.f * a - c2; row[0]  = 3.f * a - 2.f * c2; }
                if (bxR) { float a = row[33], c2 = row[32];
                           row[34] = 2.f * a - c2; row[35] = 3.f * a - 2.f * c2; }
            }
            __syncwarp();
        }
        if (byL | byR) {
            for (int xx = tx; xx < 36; xx += 32) {
                float* p = sl + xx;
                if (byL) { float a = p[2 * 37],  c2 = p[3 * 37];
                           p[37]      = 2.f * a - c2; p[0]       = 3.f * a - 2.f * c2; }
                if (byR) { float a = p[17 * 37], c2 = p[16 * 37];
                           p[18 * 37] = 2.f * a - c2; p[19 * 37] = 3.f * a - 2.f * c2; }
            }
        }
    };

    for (int gz = z0 - 2; gz <= z0 + 1; gz++)
        load_slice(gz, s + ((gz + 16) & 7) * SL);
    __syncthreads();
    if (edge) {
        if (tid < 32)
            for (int gz = z0 - 2; gz <= z0 + 1; gz++)
                fixup(s + ((gz + 16) & 7) * SL);
        __syncthreads();
    }

    const int gx = bx0 + tx;
    const float fxc = (gx == 0 || gx == DD - 1) ? 2.f : 1.f;
    const int y4 = tyq * 4;
    const int coff = (y4 + 2) * 37 + tx + 2;

    for (int z = z0; z < z0 + 20; z++) {
        load_slice(z + 2, s + ((z + 18) & 7) * SL);
        __syncthreads();
        if (edge) {
            if (tid < 32) fixup(s + ((z + 18) & 7) * SL);
            __syncthreads();
        }

        const float* sm2 = s + ((z + 14) & 7) * SL;
        const float* sm1 = s + ((z + 15) & 7) * SL;
        const float* sc  = s + ((z + 16) & 7) * SL;
        const float* sp1 = s + ((z + 17) & 7) * SL;
        const float* sp2 = s + ((z + 18) & 7) * SL;
        const float fz = (z == 0 || z == DD - 1) ? 2.f : 1.f;

        float h[4][6];
#pragma unroll
        for (int v = 0; v < 4; v++) {
            const int c = coff + v * 37;
            const int gy = by0 + y4 + v;
            const float fy = (gy == 0 || gy == DD - 1) ? 2.f : 1.f;
            float cc = sc[c];
            h[v][0] = fz * 0.25f * (sp2[c] - 2.f * cc + sm2[c]);
            h[v][1] = 0.25f * (sp1[c + 37] - sp1[c - 37] - sm1[c + 37] + sm1[c - 37]);
            h[v][2] = 0.25f * (sp1[c + 1] - sp1[c - 1] - sm1[c + 1] + sm1[c - 1]);
            h[v][3] = fy * 0.25f * (sc[c + 74] - 2.f * cc + sc[c - 74]);
            h[v][4] = 0.25f * (sc[c + 38] - sc[c + 36] - sc[c - 36] + sc[c - 38]);
            h[v][5] = fxc * 0.25f * (sc[c + 2] - 2.f * cc + sc[c - 2]);
        }

        float a2[4];
#pragma unroll
        for (int v = 0; v < 4; v++) a2[v] = sb2s[0];

#pragma unroll
        for (int o = 0; o < 10; o++) {
            float wr0 = sw1[o * 6 + 0], wr1 = sw1[o * 6 + 1], wr2 = sw1[o * 6 + 2];
            float wr3 = sw1[o * 6 + 3], wr4 = sw1[o * 6 + 4], wr5 = sw1[o * 6 + 5];
            const float bo  = sb1[o];
            const float w2o = sw2[o];
#pragma unroll
            for (int v = 0; v < 4; v++) {
                float t = bo;
                t = fmaf(wr0, h[v][0], t);
                t = fmaf(wr1, h[v][1], t);
                t = fmaf(wr2, h[v][2], t);
                t = fmaf(wr3, h[v][3], t);
                t = fmaf(wr4, h[v][4], t);
                t = fmaf(wr5, h[v][5], t);
                a2[v] = fmaf(w2o, fmaxf(t, 0.f), a2[v]);
            }
        }

#pragma unroll
        for (int v = 0; v < 4; v++) {
            float sg = 1.f / (1.f + __expf(-a2[v]));
            out[(((size_t)b * DD + z) * DD + (by0 + y4 + v)) * DD + gx] = sg;
        }
    }
}

// ---------------------------------------------------------------------------
// Launch: inputs per metadata order: x, conv_w, w1, b1, w2, b2
// ---------------------------------------------------------------------------
extern "C" void kernel_launch(void* const* d_in, const int* in_sizes, int n_in,
                              void* d_out, int out_size)
{
    const float* x  = (const float*)d_in[0];
    const float* cw = (const float*)d_in[1];
    const float* w1 = (const float*)d_in[2];
    const float* b1 = (const float*)d_in[3];
    const float* w2 = (const float*)d_in[4];
    const float* b2 = (const float*)d_in[5];
    float* out = (float*)d_out;

    // conv: grid x:5 (32x), y:5 (32y), z: 2 batches * 8 z-chunks of 20
    conv3d_kernel<<<dim3(5, 5, 16), dim3(4, 32, 1)>>>(x, cw);
    // hess: grid x:5, y:10 (16y), z: 2*8
    hess_mlp_kernel<<<dim3(5, 10, 16), dim3(32, 4, 1)>>>(w1, b1, w2, b2, out);
}

// round 6
// speedup vs baseline: 1.8395x; 1.0126x over previous
#include <cuda_runtime.h>
#include <math.h>

#define DD 160
#define SL 740        // hess slice: 20 rows * 37 stride
#define CSL (36*40)   // conv slice: 36 rows * 40 stride
typedef unsigned long long u64;

// Scratch for conv output y [B=2, 160,160,160]
static __device__ float g_y[2 * DD * DD * DD];

static __device__ __forceinline__ int clampi(int v) {
    return min(DD - 1, max(0, v));
}

__device__ __forceinline__ u64 pack2(float lo, float hi) {
    u64 r; asm("mov.b64 %0, {%1, %2};" : "=l"(r) : "f"(lo), "f"(hi)); return r;
}
__device__ __forceinline__ void unpack2(u64 v, float &lo, float &hi) {
    asm("mov.b64 {%0, %1}, %2;" : "=f"(lo), "=f"(hi) : "l"(v));
}
__device__ __forceinline__ u64 ffma2(u64 a, u64 b, u64 c) {
    u64 d; asm("fma.rn.f32x2 %0, %1, %2, %3;" : "=l"(d) : "l"(a), "l"(b), "l"(c));
    return d;
}

// ---------------------------------------------------------------------------
// Pass 1: z-marching 3D conv 5x5x5, replicate padding, packed f32x2 FMA.
// Block 128 thr (4tx x 32ty). Tile 32x x 32y, marches 20 z (+4 warmup).
// Rolling acc2[5][4] (u64 pairs); 2-slot smem ring.
// ---------------------------------------------------------------------------
__global__ __launch_bounds__(128) void conv3d_kernel(
    const float* __restrict__ x, const float* __restrict__ w)
{
    __shared__ float s[2 * CSL];       // 11.5 KB
    __shared__ u64 ws2[25 * 8];        // weight rows {w,w}, padded stride 8

    const int tx  = threadIdx.x;       // 0..3 (x group of 8)
    const int ty  = threadIdx.y;       // 0..31
    const int tid = ty * 4 + tx;

    const int bx0 = blockIdx.x * 32;
    const int by0 = blockIdx.y * 32;
    const int b   = blockIdx.z >> 3;
    const int z0  = (blockIdx.z & 7) * 20;

    const float* xb = x + (size_t)b * DD * DD * DD;
    float* yb = g_y + (size_t)b * DD * DD * DD;

    if (tid < 125) {
        float wv = w[tid];
        ws2[(tid / 5) * 8 + tid % 5] = pack2(wv, wv);
    }

    // Load table: 36*36 = 1296 slice elems / 128 threads -> 11 entries
    int lsm[11], lgm[11];
#pragma unroll
    for (int k = 0; k < 11; k++) {
        int idx = tid + k * 128;
        if (idx < 1296) {
            int sy = idx / 36, sx = idx - sy * 36;
            lsm[k] = sy * 40 + sx;
            lgm[k] = clampi(by0 + sy - 2) * DD + clampi(bx0 + sx - 2);
        } else lsm[k] = -1;
    }

    u64 acc2[5][4];
#pragma unroll
    for (int g = 0; g < 5; g++)
#pragma unroll
        for (int o = 0; o < 4; o++) acc2[g][o] = 0ull;

    const int xoff = tx * 8;
    const int rowbase = ty * 40 + xoff;

    for (int i = 0; i < 24; i++) {            // step z = z0-4+i
        const int z = z0 - 4 + i;
        float* snew = s + (i & 1) * CSL;
        {   // load slice z+2 (clamped)
            const float* base = xb + (size_t)clampi(z + 2) * (DD * DD);
#pragma unroll
            for (int k = 0; k < 11; k++)
                if (lsm[k] >= 0) snew[lsm[k]] = __ldg(base + lgm[k]);
        }
        __syncthreads();

#pragma unroll
        for (int dy = 0; dy < 5; dy++) {
            const float* row = snew + rowbase + dy * 40;
            float4 ra = *(const float4*)(row);
            float4 rb = *(const float4*)(row + 4);
            float4 rc = *(const float4*)(row + 8);
            float r[12] = {ra.x, ra.y, ra.z, ra.w, rb.x, rb.y, rb.z, rb.w,
                           rc.x, rc.y, rc.z, rc.w};
            u64 p[11];
#pragma unroll
            for (int j = 0; j < 11; j++) p[j] = pack2(r[j], r[j + 1]);
#pragma unroll
            for (int g = 0; g < 5; g++) {
                const u64* wr = ws2 + ((4 - g) * 5 + dy) * 8;
                ulonglong2 wA = *(const ulonglong2*)wr;
                ulonglong2 wB = *(const ulonglong2*)(wr + 2);
                u64 w4 = wr[4];
#pragma unroll
                for (int o2 = 0; o2 < 4; o2++) {
                    u64 a = acc2[g][o2];
                    a = ffma2(wA.x, p[o2 * 2 + 0], a);
                    a = ffma2(wA.y, p[o2 * 2 + 1], a);
                    a = ffma2(wB.x, p[o2 * 2 + 2], a);
                    a = ffma2(wB.y, p[o2 * 2 + 3], a);
                    a = ffma2(w4,   p[o2 * 2 + 4], a);
                    acc2[g][o2] = a;
                }
            }
        }

        if (z >= z0) {
            float* orow = yb + (((size_t)z * DD) + (by0 + ty)) * DD + bx0 + xoff;
            float o0, o1, o2v, o3, o4, o5, o6, o7;
            unpack2(acc2[0][0], o0, o1);
            unpack2(acc2[0][1], o2v, o3);
            unpack2(acc2[0][2], o4, o5);
            unpack2(acc2[0][3], o6, o7);
            float4 v0 = {o0, o1, o2v, o3};
            float4 v1 = {o4, o5, o6, o7};
            ((float4*)orow)[0] = v0;
            ((float4*)orow)[1] = v1;
        }
#pragma unroll
        for (int g = 0; g < 4; g++)
#pragma unroll
            for (int o = 0; o < 4; o++) acc2[g][o] = acc2[g + 1][o];
#pragma unroll
        for (int o = 0; o < 4; o++) acc2[4][o] = 0ull;
    }
}

// ---------------------------------------------------------------------------
// Pass 2: z-marching Hessian + MLP (unchanged from R5).
// ---------------------------------------------------------------------------
__global__ __launch_bounds__(128) void hess_mlp_kernel(
    const float* __restrict__ w1, const float* __restrict__ b1,
    const float* __restrict__ w2, const float* __restrict__ b2,
    float* __restrict__ out)
{
    __shared__ float s[8 * SL];
    __shared__ float sw1[60], sb1[10], sw2[10], sb2s[1];

    const int tx  = threadIdx.x;   // 0..31
    const int tyq = threadIdx.y;   // 0..3 (warp id)
    const int tid = tyq * 32 + tx;

    const int bx0 = blockIdx.x * 32;
    const int by0 = blockIdx.y * 16;
    const int b   = blockIdx.z >> 3;
    const int z0  = (blockIdx.z & 7) * 20;

    const float* yb = g_y + (size_t)b * DD * DD * DD;

    if (tid < 60)       sw1[tid] = w1[tid];
    else if (tid < 70)  sb1[tid - 60] = b1[tid - 60];
    else if (tid < 80)  sw2[tid - 70] = w2[tid - 70];
    else if (tid == 80) sb2s[0] = b2[0];

    int lsm[6], lgm[6];
#pragma unroll
    for (int k = 0; k < 6; k++) {
        int idx = tid + k * 128;
        if (idx < 720) {
            int sy = idx / 36, sx = idx - sy * 36;
            lsm[k] = sy * 37 + sx;
            lgm[k] = clampi(by0 + sy - 2) * DD + clampi(bx0 + sx - 2);
        } else { lsm[k] = -1; lgm[k] = 0; }
    }

    const bool bxL = (bx0 == 0), bxR = (bx0 + 32 == DD);
    const bool byL = (by0 == 0), byR = (by0 + 16 == DD);
    const bool edge = bxL | bxR | byL | byR;

    auto load_slice = [&](int gz, float* dst) {
        if ((unsigned)gz < DD) {
            const float* base = yb + (size_t)gz * (DD * DD);
#pragma unroll
            for (int k = 0; k < 6; k++)
                if (lsm[k] >= 0) dst[lsm[k]] = __ldg(base + lgm[k]);
        } else {
            int e; const float *p0, *p1;
            if (gz < 0) { e = -gz; p0 = yb; p1 = yb + DD * DD; }
            else        { e = gz - (DD - 1);
                          p0 = yb + (size_t)(DD - 1) * DD * DD;
                          p1 = yb + (size_t)(DD - 2) * DD * DD; }
            float w0 = 1.f + (float)e, w1n = -(float)e;
#pragma unroll
            for (int k = 0; k < 6; k++)
                if (lsm[k] >= 0)
                    dst[lsm[k]] = w0 * __ldg(p0 + lgm[k]) + w1n * __ldg(p1 + lgm[k]);
        }
    };

    auto fixup = [&](float* sl) {
        if (bxL | bxR) {
            if (tx < 20) {
                float* row = sl + tx * 37;
                if (bxL) { float a = row[2],  c2 = row[3];
                           row[1]  = 2.f * a - c2; row[0]  = 3.f * a - 2.f * c2; }
                if (bxR) { float a = row[33], c2 = row[32];
                           row[34] = 2.f * a - c2; row[35] = 3.f * a - 2.f * c2; }
            }
            __syncwarp();
        }
        if (byL | byR) {
            for (int xx = tx; xx < 36; xx += 32) {
                float* p = sl + xx;
                if (byL) { float a = p[2 * 37],  c2 = p[3 * 37];
                           p[37]      = 2.f * a - c2; p[0]       = 3.f * a - 2.f * c2; }
                if (byR) { float a = p[17 * 37], c2 = p[16 * 37];
                           p[18 * 37] = 2.f * a - c2; p[19 * 37] = 3.f * a - 2.f * c2; }
            }
        }
    };

    for (int gz = z0 - 2; gz <= z0 + 1; gz++)
        load_slice(gz, s + ((gz + 16) & 7) * SL);
    __syncthreads();
    if (edge) {
        if (tid < 32)
            for (int gz = z0 - 2; gz <= z0 + 1; gz++)
                fixup(s + ((gz + 16) & 7) * SL);
        __syncthreads();
    }

    const int gx = bx0 + tx;
    const float fxc = (gx == 0 || gx == DD - 1) ? 2.f : 1.f;
    const int y4 = tyq * 4;
    const int coff = (y4 + 2) * 37 + tx + 2;

    for (int z = z0; z < z0 + 20; z++) {
        load_slice(z + 2, s + ((z + 18) & 7) * SL);
        __syncthreads();
        if (edge) {
            if (tid < 32) fixup(s + ((z + 18) & 7) * SL);
            __syncthreads();
        }

        const float* sm2 = s + ((z + 14) & 7) * SL;
        const float* sm1 = s + ((z + 15) & 7) * SL;
        const float* sc  = s + ((z + 16) & 7) * SL;
        const float* sp1 = s + ((z + 17) & 7) * SL;
        const float* sp2 = s + ((z + 18) & 7) * SL;
        const float fz = (z == 0 || z == DD - 1) ? 2.f : 1.f;

        float h[4][6];
#pragma unroll
        for (int v = 0; v < 4; v++) {
            const int c = coff + v * 37;
            const int gy = by0 + y4 + v;
            const float fy = (gy == 0 || gy == DD - 1) ? 2.f : 1.f;
            float cc = sc[c];
            h[v][0] = fz * 0.25f * (sp2[c] - 2.f * cc + sm2[c]);
            h[v][1] = 0.25f * (sp1[c + 37] - sp1[c - 37] - sm1[c + 37] + sm1[c - 37]);
            h[v][2] = 0.25f * (sp1[c + 1] - sp1[c - 1] - sm1[c + 1] + sm1[c - 1]);
            h[v][3] = fy * 0.25f * (sc[c + 74] - 2.f * cc + sc[c - 74]);
            h[v][4] = 0.25f * (sc[c + 38] - sc[c + 36] - sc[c - 36] + sc[c - 38]);
            h[v][5] = fxc * 0.25f * (sc[c + 2] - 2.f * cc + sc[c - 2]);
        }

        float a2[4];
#pragma unroll
        for (int v = 0; v < 4; v++) a2[v] = sb2s[0];

#pragma unroll
        for (int o = 0; o < 10; o++) {
            float wr0 = sw1[o * 6 + 0], wr1 = sw1[o * 6 + 1], wr2 = sw1[o * 6 + 2];
            float wr3 = sw1[o * 6 + 3], wr4 = sw1[o * 6 + 4], wr5 = sw1[o * 6 + 5];
            const float bo  = sb1[o];
            const float w2o = sw2[o];
#pragma unroll
            for (int v = 0; v < 4; v++) {
                float t = bo;
                t = fmaf(wr0, h[v][0], t);
                t = fmaf(wr1, h[v][1], t);
                t = fmaf(wr2, h[v][2], t);
                t = fmaf(wr3, h[v][3], t);
                t = fmaf(wr4, h[v][4], t);
                t = fmaf(wr5, h[v][5], t);
                a2[v] = fmaf(w2o, fmaxf(t, 0.f), a2[v]);
            }
        }

#pragma unroll
        for (int v = 0; v < 4; v++) {
            float sg = 1.f / (1.f + __expf(-a2[v]));
            out[(((size_t)b * DD + z) * DD + (by0 + y4 + v)) * DD + gx] = sg;
        }
    }
}

// ---------------------------------------------------------------------------
// Launch: inputs per metadata order: x, conv_w, w1, b1, w2, b2
// ---------------------------------------------------------------------------
extern "C" void kernel_launch(void* const* d_in, const int* in_sizes, int n_in,
                              void* d_out, int out_size)
{
    const float* x  = (const float*)d_in[0];
    const float* cw = (const float*)d_in[1];
    const float* w1 = (const float*)d_in[2];
    const float* b1 = (const float*)d_in[3];
    const float* w2 = (const float*)d_in[4];
    const float* b2 = (const float*)d_in[5];
    float* out = (float*)d_out;

    conv3d_kernel<<<dim3(5, 5, 16), dim3(4, 32, 1)>>>(x, cw);
    hess_mlp_kernel<<<dim3(5, 10, 16), dim3(32, 4, 1)>>>(w1, b1, w2, b2, out);
}

// round 7
// speedup vs baseline: 2.2621x; 1.2297x over previous
#include <cuda_runtime.h>
#include <math.h>

#define DD 160
#define SL 740        // hess slice: 20 rows * 37 stride
#define CSL (36*40)   // conv slice: 36 rows * 40 stride

// Scratch for conv output y [B=2, 160,160,160]
static __device__ float g_y[2 * DD * DD * DD];

static __device__ __forceinline__ int clampi(int v) {
    return min(DD - 1, max(0, v));
}

// ---------------------------------------------------------------------------
// Pass 1: z-marching 3D conv 5x5x5, replicate padding, scalar FFMA.
// Block 128 thr (4tx x 32ty). Tile 32x x 32y, chunk 10 z (+4 warmup).
// Rolling acc[5][8]; 2-slot smem ring. Warmup/tail generation bounds are
// compile-time (static unroll) -> exact 125 FMA per output, zero waste.
// ---------------------------------------------------------------------------
__global__ __launch_bounds__(128) void conv3d_kernel(
    const float* __restrict__ x, const float* __restrict__ w)
{
    __shared__ float s[2 * CSL];      // 11.5 KB
    __shared__ float wsp[25 * 8];     // weight rows padded to stride 8

    const int tx  = threadIdx.x;      // 0..3 (x group of 8)
    const int ty  = threadIdx.y;      // 0..31
    const int tid = ty * 4 + tx;

    const int bx0 = blockIdx.x * 32;
    const int by0 = blockIdx.y * 32;
    const int b   = blockIdx.z >> 4;
    const int z0  = (blockIdx.z & 15) * 10;

    const float* xb = x + (size_t)b * DD * DD * DD;
    float* yb = g_y + (size_t)b * DD * DD * DD;

    if (tid < 125) wsp[(tid / 5) * 8 + tid % 5] = w[tid];

    // Load table: 36*36 = 1296 slice elems / 128 threads -> 11 entries
    int lsm[11], lgm[11];
#pragma unroll
    for (int k = 0; k < 11; k++) {
        int idx = tid + k * 128;
        if (idx < 1296) {
            int sy = idx / 36, sx = idx - sy * 36;
            lsm[k] = sy * 40 + sx;
            lgm[k] = clampi(by0 + sy - 2) * DD + clampi(bx0 + sx - 2);
        } else lsm[k] = -1;
    }

    float acc[5][8];
#pragma unroll
    for (int g = 0; g < 5; g++)
#pragma unroll
        for (int o = 0; o < 8; o++) acc[g][o] = 0.f;

    const int xoff = tx * 8;
    const int rowbase = ty * 40 + xoff;

    auto load_slice = [&](int i) {
        float* snew = s + (i & 1) * CSL;
        const float* base = xb + (size_t)clampi(z0 - 2 + i) * (DD * DD);
#pragma unroll
        for (int k = 0; k < 11; k++)
            if (lsm[k] >= 0) snew[lsm[k]] = __ldg(base + lgm[k]);
    };

    // FMA for generations [gmin, gmax) from slice slot (i&1).
    auto fma_gens = [&](int i, int gmin, int gmax) {
#pragma unroll
        for (int dy = 0; dy < 5; dy++) {
            const float* row = s + (i & 1) * CSL + rowbase + dy * 40;
            float4 ra = *(const float4*)(row);
            float4 rb = *(const float4*)(row + 4);
            float4 rc = *(const float4*)(row + 8);
            float r[12] = {ra.x, ra.y, ra.z, ra.w, rb.x, rb.y, rb.z, rb.w,
                           rc.x, rc.y, rc.z, rc.w};
#pragma unroll
            for (int g = 0; g < 5; g++) {
                if (g >= gmin && g < gmax) {
                    const float* wr = wsp + ((4 - g) * 5 + dy) * 8;
                    float4 wv = *(const float4*)wr;
                    float w4 = wr[4];
#pragma unroll
                    for (int o = 0; o < 8; o++) {
                        float a = acc[g][o];
                        a = fmaf(wv.x, r[o + 0], a);
                        a = fmaf(wv.y, r[o + 1], a);
                        a = fmaf(wv.z, r[o + 2], a);
                        a = fmaf(wv.w, r[o + 3], a);
                        a = fmaf(w4,   r[o + 4], a);
                        acc[g][o] = a;
                    }
                }
            }
        }
    };

    auto shift = [&]() {
#pragma unroll
        for (int g = 0; g < 4; g++)
#pragma unroll
            for (int o = 0; o < 8; o++) acc[g][o] = acc[g + 1][o];
#pragma unroll
        for (int o = 0; o < 8; o++) acc[4][o] = 0.f;
    };

    auto store_out = [&](int z) {
        float* orow = yb + (((size_t)z * DD) + (by0 + ty)) * DD + bx0 + xoff;
        float4 v0 = {acc[0][0], acc[0][1], acc[0][2], acc[0][3]};
        float4 v1 = {acc[0][4], acc[0][5], acc[0][6], acc[0][7]};
        ((float4*)orow)[0] = v0;
        ((float4*)orow)[1] = v1;
    };

    // Warmup: steps i=0..3, generations g >= 4-i (static bounds)
#pragma unroll
    for (int i = 0; i < 4; i++) {
        load_slice(i);
        __syncthreads();
        fma_gens(i, 4 - i, 5);
        shift();
    }
    // Steady: steps i=4..9, all generations
#pragma unroll 1
    for (int i = 4; i < 10; i++) {
        load_slice(i);
        __syncthreads();
        fma_gens(i, 0, 5);
        store_out(z0 - 4 + i);
        shift();
    }
    // Tail: steps i=10..13, generations g < 14-i (static bounds)
#pragma unroll
    for (int i = 10; i < 14; i++) {
        load_slice(i);
        __syncthreads();
        fma_gens(i, 0, 14 - i);
        store_out(z0 - 4 + i);
        shift();
    }
}

// ---------------------------------------------------------------------------
// Pass 2: z-marching Hessian + MLP. Chunk 10 z (grid 1600) for occupancy.
// ---------------------------------------------------------------------------
__global__ __launch_bounds__(128) void hess_mlp_kernel(
    const float* __restrict__ w1, const float* __restrict__ b1,
    const float* __restrict__ w2, const float* __restrict__ b2,
    float* __restrict__ out)
{
    __shared__ float s[8 * SL];
    __shared__ float sw1[60], sb1[10], sw2[10], sb2s[1];

    const int tx  = threadIdx.x;   // 0..31
    const int tyq = threadIdx.y;   // 0..3 (warp id)
    const int tid = tyq * 32 + tx;

    const int bx0 = blockIdx.x * 32;
    const int by0 = blockIdx.y * 16;
    const int b   = blockIdx.z >> 4;
    const int z0  = (blockIdx.z & 15) * 10;

    const float* yb = g_y + (size_t)b * DD * DD * DD;

    if (tid < 60)       sw1[tid] = w1[tid];
    else if (tid < 70)  sb1[tid - 60] = b1[tid - 60];
    else if (tid < 80)  sw2[tid - 70] = w2[tid - 70];
    else if (tid == 80) sb2s[0] = b2[0];

    int lsm[6], lgm[6];
#pragma unroll
    for (int k = 0; k < 6; k++) {
        int idx = tid + k * 128;
        if (idx < 720) {
            int sy = idx / 36, sx = idx - sy * 36;
            lsm[k] = sy * 37 + sx;
            lgm[k] = clampi(by0 + sy - 2) * DD + clampi(bx0 + sx - 2);
        } else { lsm[k] = -1; lgm[k] = 0; }
    }

    const bool bxL = (bx0 == 0), bxR = (bx0 + 32 == DD);
    const bool byL = (by0 == 0), byR = (by0 + 16 == DD);
    const bool edge = bxL | bxR | byL | byR;

    auto load_slice = [&](int gz, float* dst) {
        if ((unsigned)gz < DD) {
            const float* base = yb + (size_t)gz * (DD * DD);
#pragma unroll
            for (int k = 0; k < 6; k++)
                if (lsm[k] >= 0) dst[lsm[k]] = __ldg(base + lgm[k]);
        } else {
            int e; const float *p0, *p1;
            if (gz < 0) { e = -gz; p0 = yb; p1 = yb + DD * DD; }
            else        { e = gz - (DD - 1);
                          p0 = yb + (size_t)(DD - 1) * DD * DD;
                          p1 = yb + (size_t)(DD - 2) * DD * DD; }
            float w0 = 1.f + (float)e, w1n = -(float)e;
#pragma unroll
            for (int k = 0; k < 6; k++)
                if (lsm[k] >= 0)
                    dst[lsm[k]] = w0 * __ldg(p0 + lgm[k]) + w1n * __ldg(p1 + lgm[k]);
        }
    };

    auto fixup = [&](float* sl) {
        if (bxL | bxR) {
            if (tx < 20) {
                float* row = sl + tx * 37;
                if (bxL) { float a = row[2],  c2 = row[3];
                           row[1]  = 2.f * a - c2; row[0]  = 3.f * a - 2.f * c2; }
                if (bxR) { float a = row[33], c2 = row[32];
                           row[34] = 2.f * a - c2; row[35] = 3.f * a - 2.f * c2; }
            }
            __syncwarp();
        }
        if (byL | byR) {
            for (int xx = tx; xx < 36; xx += 32) {
                float* p = sl + xx;
                if (byL) { float a = p[2 * 37],  c2 = p[3 * 37];
                           p[37]      = 2.f * a - c2; p[0]       = 3.f * a - 2.f * c2; }
                if (byR) { float a = p[17 * 37], c2 = p[16 * 37];
                           p[18 * 37] = 2.f * a - c2; p[19 * 37] = 3.f * a - 2.f * c2; }
            }
        }
    };

    for (int gz = z0 - 2; gz <= z0 + 1; gz++)
        load_slice(gz, s + ((gz + 16) & 7) * SL);
    __syncthreads();
    if (edge) {
        if (tid < 32)
            for (int gz = z0 - 2; gz <= z0 + 1; gz++)
                fixup(s + ((gz + 16) & 7) * SL);
        __syncthreads();
    }

    const int gx = bx0 + tx;
    const float fxc = (gx == 0 || gx == DD - 1) ? 2.f : 1.f;
    const int y4 = tyq * 4;
    const int coff = (y4 + 2) * 37 + tx + 2;

    for (int z = z0; z < z0 + 10; z++) {
        load_slice(z + 2, s + ((z + 18) & 7) * SL);
        __syncthreads();
        if (edge) {
            if (tid < 32) fixup(s + ((z + 18) & 7) * SL);
            __syncthreads();
        }

        const float* sm2 = s + ((z + 14) & 7) * SL;
        const float* sm1 = s + ((z + 15) & 7) * SL;
        const float* sc  = s + ((z + 16) & 7) * SL;
        const float* sp1 = s + ((z + 17) & 7) * SL;
        const float* sp2 = s + ((z + 18) & 7) * SL;
        const float fz = (z == 0 || z == DD - 1) ? 2.f : 1.f;

        float h[4][6];
#pragma unroll
        for (int v = 0; v < 4; v++) {
            const int c = coff + v * 37;
            const int gy = by0 + y4 + v;
            const float fy = (gy == 0 || gy == DD - 1) ? 2.f : 1.f;
            float cc = sc[c];
            h[v][0] = fz * 0.25f * (sp2[c] - 2.f * cc + sm2[c]);
            h[v][1] = 0.25f * (sp1[c + 37] - sp1[c - 37] - sm1[c + 37] + sm1[c - 37]);
            h[v][2] = 0.25f * (sp1[c + 1] - sp1[c - 1] - sm1[c + 1] + sm1[c - 1]);
            h[v][3] = fy * 0.25f * (sc[c + 74] - 2.f * cc + sc[c - 74]);
            h[v][4] = 0.25f * (sc[c + 38] - sc[c + 36] - sc[c - 36] + sc[c - 38]);
            h[v][5] = fxc * 0.25f * (sc[c + 2] - 2.f * cc + sc[c - 2]);
        }

        float a2[4];
#pragma unroll
        for (int v = 0; v < 4; v++) a2[v] = sb2s[0];

#pragma unroll
        for (int o = 0; o < 10; o++) {
            float wr0 = sw1[o * 6 + 0], wr1 = sw1[o * 6 + 1], wr2 = sw1[o * 6 + 2];
            float wr3 = sw1[o * 6 + 3], wr4 = sw1[o * 6 + 4], wr5 = sw1[o * 6 + 5];
            const float bo  = sb1[o];
            const float w2o = sw2[o];
#pragma unroll
            for (int v = 0; v < 4; v++) {
                float t = bo;
                t = fmaf(wr0, h[v][0], t);
                t = fmaf(wr1, h[v][1], t);
                t = fmaf(wr2, h[v][2], t);
                t = fmaf(wr3, h[v][3], t);
                t = fmaf(wr4, h[v][4], t);
                t = fmaf(wr5, h[v][5], t);
                a2[v] = fmaf(w2o, fmaxf(t, 0.f), a2[v]);
            }
        }

#pragma unroll
        for (int v = 0; v < 4; v++) {
            float sg = 1.f / (1.f + __expf(-a2[v]));
            out[(((size_t)b * DD + z) * DD + (by0 + y4 + v)) * DD + gx] = sg;
        }
    }
}

// ---------------------------------------------------------------------------
// Launch: inputs per metadata order: x, conv_w, w1, b1, w2, b2
// ---------------------------------------------------------------------------
extern "C" void kernel_launch(void* const* d_in, const int* in_sizes, int n_in,
                              void* d_out, int out_size)
{
    const float* x  = (const float*)d_in[0];
    const float* cw = (const float*)d_in[1];
    const float* w1 = (const float*)d_in[2];
    const float* b1 = (const float*)d_in[3];
    const float* w2 = (const float*)d_in[4];
    const float* b2 = (const float*)d_in[5];
    float* out = (float*)d_out;

    // conv: grid x:5 (32x), y:5 (32y), z: 2 batches * 16 z-chunks of 10
    conv3d_kernel<<<dim3(5, 5, 32), dim3(4, 32, 1)>>>(x, cw);
    // hess: grid x:5, y:10 (16y), z: 2 * 16
    hess_mlp_kernel<<<dim3(5, 10, 32), dim3(32, 4, 1)>>>(w1, b1, w2, b2, out);
}